// round 16
// baseline (speedup 1.0000x reference)
#include <cuda_runtime.h>
#include <cuda_fp16.h>
#include <math.h>
#include <cstdint>

// ---------------------------------------------------------------------------
// Problem constants
// ---------------------------------------------------------------------------
#define NMAX   50000
#define EAMAX  850000   // 800000 edges + 50000 self loops
#define NBSCAN ((NMAX + 1023) / 1024)

// ---------------------------------------------------------------------------
// Static device scratch
// ---------------------------------------------------------------------------
__device__ int   g_src[EAMAX];
__device__ int   g_dst[EAMAX];
__device__ int   g_cnt[NMAX];
__device__ int   g_rowptr[NMAX + 1];
__device__ int   g_wpos[NMAX];
__device__ int   g_srcsorted[EAMAX];
__device__ int   g_bsum[NBSCAN + 1];
__device__ int   g_is64flag;
__device__ __half g_hh [(size_t)NMAX * 256];  // GEMM output h (gather source)
__device__ __half g_x1h[(size_t)NMAX * 256];  // layer-1 output x1, fp16
__device__ __half g_xh [(size_t)NMAX * 128];  // input x, fp16
__device__ float g_as [NMAX * 2];             // layer-1 alpha_src
__device__ float g_ad [NMAX * 2];             // layer-1 alpha_dst
__device__ float g_as2[NMAX * 4];             // layer-2 alphas (mu0,mu1,ls0,ls1)
__device__ float g_ad2[NMAX * 4];
// fp16 weights (transposed [Nout][K])
__device__ __half g_w1[256 * 128];            // W1^T
__device__ __half g_w2[256 * 256];            // [W_mu|W_ls]^T

// ===========================================================================
// PTX helpers — baseline ISA only (valid at ptxas target sm_103)
// ===========================================================================
__device__ __forceinline__ uint32_t smem_to_u32(const void* p) {
    uint32_t a;
    asm("{ .reg .u64 t; cvta.to.shared.u64 t, %1; cvt.u32.u64 %0, t; }"
        : "=r"(a) : "l"(p));
    return a;
}
#define SMEM_SWIZZLE_128B(off) ((off) ^ (((off) >> 3) & 0x70))

__device__ __forceinline__ void cp_async16(uint32_t saddr, const void* gaddr) {
    asm volatile("cp.async.cg.shared.global [%0], [%1], 16;"
                 :: "r"(saddr), "l"(gaddr));
}
__device__ __forceinline__ void cp_commit() {
    asm volatile("cp.async.commit_group;");
}
__device__ __forceinline__ void cp_wait1() {
    asm volatile("cp.async.wait_group 1;");
}
__device__ __forceinline__ void cp_wait0() {
    asm volatile("cp.async.wait_group 0;");
}

__device__ __forceinline__ void ldsm4(uint32_t& r0, uint32_t& r1, uint32_t& r2,
                                      uint32_t& r3, uint32_t addr) {
    asm volatile("ldmatrix.sync.aligned.m8n8.x4.shared.b16 {%0,%1,%2,%3}, [%4];"
                 : "=r"(r0), "=r"(r1), "=r"(r2), "=r"(r3) : "r"(addr));
}

__device__ __forceinline__ void mma16816_f16(float* d, const uint32_t* a,
                                             const uint32_t* b) {
    asm volatile(
        "mma.sync.aligned.m16n8k16.row.col.f32.f16.f16.f32 "
        "{%0,%1,%2,%3}, {%4,%5,%6,%7}, {%8,%9}, {%0,%1,%2,%3};"
        : "+f"(d[0]), "+f"(d[1]), "+f"(d[2]), "+f"(d[3])
        : "r"(a[0]), "r"(a[1]), "r"(a[2]), "r"(a[3]), "r"(b[0]), "r"(b[1]));
}

// Non-coherent (read-only path) vector load of a gathered h row segment.
__device__ __forceinline__ uint4 ldg_nc16(const void* p) {
    uint4 v;
    asm volatile("ld.global.nc.v4.u32 {%0,%1,%2,%3}, [%4];"
                 : "=r"(v.x), "=r"(v.y), "=r"(v.z), "=r"(v.w) : "l"(p));
    return v;
}
// Streaming (evict-first) int load for read-once edge indices.
__device__ __forceinline__ int ldcs_i32(const int* p) {
    int v;
    asm volatile("ld.global.cs.s32 %0, [%1];" : "=r"(v) : "l"(p));
    return v;
}

// ---------------------------------------------------------------------------
// dtype probe + edge conversion + CSR build
// ---------------------------------------------------------------------------
__global__ void detect64(const unsigned int* __restrict__ raw)
{
    if (threadIdx.x == 0) {
        bool is64 = true;
#pragma unroll 1
        for (int w = 0; w < 64; w++)
            if (raw[2 * w + 1] != 0u) { is64 = false; break; }
        g_is64flag = is64 ? 1 : 0;
    }
}

__global__ void zero_int(int* __restrict__ p, int n)
{
    int i = blockIdx.x * blockDim.x + threadIdx.x;
    if (i < n) p[i] = 0;
}

__global__ void convert_hist(const unsigned int* __restrict__ raw, int E, int n)
{
    int idx = blockIdx.x * blockDim.x + threadIdx.x;
    int EA = E + n;
    if (idx >= EA) return;
    bool is64 = (g_is64flag != 0);
    int s, d;
    if (idx < E) {
        if (is64) {
            const unsigned long long* r64 = (const unsigned long long*)raw;
            s = (int)r64[idx];
            d = (int)r64[(size_t)E + idx];
        } else {
            s = (int)raw[idx];
            d = (int)raw[E + idx];
        }
    } else {
        s = idx - E;
        d = s;
    }
    g_src[idx] = s;
    g_dst[idx] = d;
    atomicAdd(&g_cnt[d], 1);
}

__global__ void scan_phase1(int n)
{
    __shared__ int sh[1024];
    int tid = threadIdx.x;
    int i = blockIdx.x * 1024 + tid;
    sh[tid] = (i < n) ? g_cnt[i] : 0;
    __syncthreads();
    for (int off = 1; off < 1024; off <<= 1) {
        int v = (tid >= off) ? sh[tid - off] : 0;
        __syncthreads();
        sh[tid] += v;
        __syncthreads();
    }
    if (i < n) g_rowptr[i + 1] = sh[tid];
    if (tid == 0) g_bsum[blockIdx.x] = sh[1023];
}

__global__ void scan_phase2(int nb)
{
    if (threadIdx.x == 0) {
        int run = 0;
        for (int b = 0; b < nb; b++) { int v = g_bsum[b]; g_bsum[b] = run; run += v; }
    }
}

__global__ void scan_phase3(int n)
{
    int tid = threadIdx.x;
    int i = blockIdx.x * 1024 + tid;
    if (i < n) {
        int v = g_rowptr[i + 1] + g_bsum[blockIdx.x];
        g_rowptr[i + 1] = v;
        if (i + 1 < n) g_wpos[i + 1] = v;     // wpos[j] = rowptr[j]
    }
    if (i == 0) { g_rowptr[0] = 0; g_wpos[0] = 0; }
}

__global__ void scatter_edges(int EA)
{
    int i = blockIdx.x * blockDim.x + threadIdx.x;
    if (i >= EA) return;
    int d = g_dst[i];
    int pos = atomicAdd(&g_wpos[d], 1);
    g_srcsorted[pos] = g_src[i];
}

// ---------------------------------------------------------------------------
// Prep: fused x->fp16 cast and W1 transpose+cast (independent index ranges)
// ---------------------------------------------------------------------------
__global__ void cast_prep1(const float* __restrict__ x,
                           const float* __restrict__ W1, int nx)
{
    int i = blockIdx.x * blockDim.x + threadIdx.x;
    if (i < nx) {
        g_xh[i] = __float2half_rn(x[i]);
    } else {
        int j = i - nx;                 // over 256*128
        if (j < 256 * 128) {
            int nout = j / 128, k = j % 128;
            g_w1[nout * 128 + k] = __float2half_rn(W1[k * 256 + nout]);
        }
    }
}

__global__ void prep_w2_f16(const float* __restrict__ Wmu, const float* __restrict__ Wls)
{
    int i = blockIdx.x * blockDim.x + threadIdx.x;   // over 256*256
    if (i >= 256 * 256) return;
    int nout = i / 256, k = i % 256;
    float v = (nout < 128) ? Wmu[k * 128 + nout] : Wls[k * 128 + (nout - 128)];
    g_w2[nout * 256 + k] = __float2half_rn(v);
}

// ---------------------------------------------------------------------------
// GEMM tiles: 128 rows x 64 fp16 = 16KB, SW128 swizzled, via cp.async.
// ---------------------------------------------------------------------------
#define GEMM_TILE   16384
#define GEMMF_BUF   (2 * GEMM_TILE)   // A, B
#define GEMMF_SMEM  (2 * GEMMF_BUF)   // 64KB, double buffered

__device__ __forceinline__ void stage_tile(uint32_t sdst, const void* gsrc,
                                           int stride, int row0, int rowmax,
                                           int k0, int tid)
{
#pragma unroll
    for (int c = tid; c < 1024; c += 256) {
        int r  = c >> 3;
        int ck = (c & 7) * 8;
        uint32_t off = (uint32_t)(r * 128 + ck * 2);
        off = SMEM_SWIZZLE_128B(off);
        int gr = row0 + r;
        if (gr > rowmax) gr = rowmax;
        cp_async16(sdst + off,
                   (const char*)gsrc + ((size_t)gr * stride + k0 + ck) * 2);
    }
}

// ---------------------------------------------------------------------------
// fp16 GEMM + fused epilogue (H fp16 + alpha dot products).
// RED=true  (C_HEAD=128): smem-reduce partials across the two warps/head.
// RED=false (C_HEAD=64) : single warp per (row, head) -> plain store.
// ---------------------------------------------------------------------------
template <int C_HEAD, bool DUAL, bool RED>
__global__ __launch_bounds__(256, 1)
void gemm_f16(const __half* __restrict__ A, const __half* __restrict__ B,
              __half* __restrict__ H,
              const float* __restrict__ avsA, const float* __restrict__ avdA,
              const float* __restrict__ avsB, const float* __restrict__ avdB,
              float* __restrict__ as_out, float* __restrict__ ad_out,
              int M, int K, int Ntot)
{
    extern __shared__ char smem[];
    uint32_t sb = smem_to_u32(smem);
    int tid  = threadIdx.x;
    int wid  = tid >> 5;
    int lane = tid & 31;

    int rowBase = blockIdx.y * 128;
    int colBase = blockIdx.x * 128;
    int warp_m  = (wid & 3) * 32;
    int warp_n  = (wid >> 2) * 64;

    int nchunks = K >> 6;

    {
        uint32_t b = sb;
        stage_tile(b + 0 * GEMM_TILE, A, K, rowBase, M - 1,    0, tid);
        stage_tile(b + 1 * GEMM_TILE, B, K, colBase, Ntot - 1, 0, tid);
        cp_commit();
    }

    float acc[2][8][4];
#pragma unroll
    for (int i = 0; i < 2; i++)
#pragma unroll
        for (int j = 0; j < 8; j++)
#pragma unroll
            for (int q = 0; q < 4; q++) acc[i][j][q] = 0.f;

    int lr = lane & 15;
    int lc = (lane & 16) >> 1;

    for (int ci = 0; ci < nchunks; ci++) {
        if (ci + 1 < nchunks) {
            uint32_t b = sb + ((ci + 1) & 1) * GEMMF_BUF;
            int k0 = (ci + 1) << 6;
            stage_tile(b + 0 * GEMM_TILE, A, K, rowBase, M - 1,    k0, tid);
            stage_tile(b + 1 * GEMM_TILE, B, K, colBase, Ntot - 1, k0, tid);
            cp_commit();
            cp_wait1();
        } else {
            cp_wait0();
        }
        __syncthreads();

        uint32_t buf = sb + (ci & 1) * GEMMF_BUF;
        uint32_t tA = buf, tB = buf + GEMM_TILE;

#pragma unroll
        for (int ks = 0; ks < 4; ks++) {
            int kb = ks * 16 + lc;

            uint32_t af[2][4];
#pragma unroll
            for (int mi = 0; mi < 2; mi++) {
                uint32_t off = (uint32_t)((warp_m + mi * 16 + lr) * 128 + kb * 2);
                off = SMEM_SWIZZLE_128B(off);
                ldsm4(af[mi][0], af[mi][1], af[mi][2], af[mi][3], tA + off);
            }
            uint32_t bf[8][2];
#pragma unroll
            for (int nb = 0; nb < 4; nb++) {
                uint32_t off = (uint32_t)((warp_n + nb * 16 + lr) * 128 + kb * 2);
                off = SMEM_SWIZZLE_128B(off);
                uint32_t q0, q1, q2, q3;
                ldsm4(q0, q1, q2, q3, tB + off);
                bf[2 * nb][0] = q0; bf[2 * nb + 1][0] = q1;
                bf[2 * nb][1] = q2; bf[2 * nb + 1][1] = q3;
            }
#pragma unroll
            for (int mi = 0; mi < 2; mi++)
#pragma unroll
                for (int nj = 0; nj < 8; nj++)
                    mma16816_f16(acc[mi][nj], af[mi], bf[nj]);
        }
        __syncthreads();
    }

    // ---- epilogue: H fp16 + alpha partials ----
    int trow = (lane >> 2);
    int tcol = (lane & 3) * 2;

    const float* avs;
    const float* avd;
    if (DUAL) {
        avs = (colBase < 128) ? avsA : avsB;
        avd = (colBase < 128) ? avdA : avdB;
    } else {
        avs = avsA;
        avd = avdA;
    }
    constexpr int NH = 256 / C_HEAD;

    __half2* H2 = (__half2*)H;
    int nh2 = Ntot >> 1;

    float ssum[2][2] = {{0.f, 0.f}, {0.f, 0.f}};
    float dsum[2][2] = {{0.f, 0.f}, {0.f, 0.f}};

#pragma unroll
    for (int mi = 0; mi < 2; mi++) {
        int gr0 = rowBase + warp_m + mi * 16 + trow;
        int gr1 = gr0 + 8;
#pragma unroll
        for (int nj = 0; nj < 8; nj++) {
            int gc = colBase + warp_n + nj * 8 + tcol;
            int ai = DUAL ? (gc - colBase) : gc;
            float w0s = avs[ai], w1s = avs[ai + 1];
            float w0d = avd[ai], w1d = avd[ai + 1];
            ssum[mi][0] += acc[mi][nj][0] * w0s + acc[mi][nj][1] * w1s;
            dsum[mi][0] += acc[mi][nj][0] * w0d + acc[mi][nj][1] * w1d;
            ssum[mi][1] += acc[mi][nj][2] * w0s + acc[mi][nj][3] * w1s;
            dsum[mi][1] += acc[mi][nj][2] * w0d + acc[mi][nj][3] * w1d;
            if (gr0 < M)
                H2[(size_t)gr0 * nh2 + (gc >> 1)] =
                    __floats2half2_rn(acc[mi][nj][0], acc[mi][nj][1]);
            if (gr1 < M)
                H2[(size_t)gr1 * nh2 + (gc >> 1)] =
                    __floats2half2_rn(acc[mi][nj][2], acc[mi][nj][3]);
        }
    }
#pragma unroll
    for (int mi = 0; mi < 2; mi++)
#pragma unroll
        for (int r = 0; r < 2; r++) {
            ssum[mi][r] += __shfl_xor_sync(0xffffffffu, ssum[mi][r], 1);
            ssum[mi][r] += __shfl_xor_sync(0xffffffffu, ssum[mi][r], 2);
            dsum[mi][r] += __shfl_xor_sync(0xffffffffu, dsum[mi][r], 1);
            dsum[mi][r] += __shfl_xor_sync(0xffffffffu, dsum[mi][r], 2);
        }

    if (RED) {
        float* sred = (float*)smem;           // tiles no longer needed
        if ((lane & 3) == 0) {
#pragma unroll
            for (int mi = 0; mi < 2; mi++)
#pragma unroll
                for (int r = 0; r < 2; r++) {
                    int lrow = mi * 16 + 8 * r + trow;   // 0..31
                    sred[wid * 32 + lrow]       = ssum[mi][r];
                    sred[256 + wid * 32 + lrow] = dsum[mi][r];
                }
        }
        __syncthreads();
        if (tid < 128) {
            int row = rowBase + tid;
            if (row < M) {
                int w0 = tid >> 5, lrow = tid & 31;
                int head = colBase >> 7;     // C_HEAD = 128
                float sv = sred[w0 * 32 + lrow] + sred[(w0 + 4) * 32 + lrow];
                float dv = sred[256 + w0 * 32 + lrow] +
                           sred[256 + (w0 + 4) * 32 + lrow];
                as_out[row * NH + head] = sv;
                ad_out[row * NH + head] = dv;
            }
        }
    } else {
        int head = (colBase + warp_n) / C_HEAD;
        if ((lane & 3) == 0) {
#pragma unroll
            for (int mi = 0; mi < 2; mi++) {
                int gr0 = rowBase + warp_m + mi * 16 + trow;
                int gr1 = gr0 + 8;
                if (gr0 < M) {
                    as_out[gr0 * NH + head] = ssum[mi][0];
                    ad_out[gr0 * NH + head] = dsum[mi][0];
                }
                if (gr1 < M) {
                    as_out[gr1 * NH + head] = ssum[mi][1];
                    ad_out[gr1 * NH + head] = dsum[mi][1];
                }
            }
        }
    }
}

// ---------------------------------------------------------------------------
// Softmax + aggregation (proven 256-thread shape, NATURAL node order).
// One warp per dst node; lane owns 8 contiguous channels (1 LDG.128/edge);
// (u, p) via smem broadcast; x4 unroll; vectorized alpha loads.
// srcsorted via streaming loads; h gathers via read-only (nc) path.
// ---------------------------------------------------------------------------
template <int HC, int C, bool DUAL>
__global__ __launch_bounds__(256)
void aggregate(const __half* __restrict__ h,
               const float* __restrict__ as_in,   // [n][NH]
               const float* __restrict__ ad_in,
               const float* __restrict__ biasA,
               const float* __restrict__ biasB,
               float* __restrict__ outA,
               float* __restrict__ outB,
               __half* __restrict__ outH,
               int n)
{
    constexpr int NH = HC / C;
    __shared__ int   sh_u[8][32];
    __shared__ float sh_p[8][32][NH];

    int warp = threadIdx.x >> 5;
    int wid  = (blockIdx.x * blockDim.x + threadIdx.x) >> 5;
    int lane = threadIdx.x & 31;
    if (wid >= n) return;

    int s = g_rowptr[wid];
    int e = g_rowptr[wid + 1];

    int c0 = 8 * lane;                   // lane's first channel
    int hd = c0 / C;                     // lane's head

    float ad[NH];
    if (NH == 2) {
        float2 t = *(const float2*)&ad_in[wid * 2];
        ad[0] = t.x; ad[1] = t.y;
    } else {
        float4 t = *(const float4*)&ad_in[wid * 4];
        ad[0] = t.x; ad[1] = t.y; ad[2] = t.z; ad[3] = t.w;
    }

    float acc[8];
#pragma unroll
    for (int t = 0; t < 8; t++) acc[t] = 0.f;
    float den[NH];
#pragma unroll
    for (int nh = 0; nh < NH; nh++) den[nh] = 0.f;

    for (int base = s; base < e; base += 32) {
        int cnt = e - base; if (cnt > 32) cnt = 32;
        if (lane < cnt) {
            int u = ldcs_i32(&g_srcsorted[base + lane]);   // streaming, read-once
            sh_u[warp][lane] = u;
            float av[NH];
            if (NH == 2) {
                float2 t = *(const float2*)&as_in[u * 2];
                av[0] = t.x; av[1] = t.y;
            } else {
                float4 t = *(const float4*)&as_in[u * 4];
                av[0] = t.x; av[1] = t.y; av[2] = t.z; av[3] = t.w;
            }
#pragma unroll
            for (int nh = 0; nh < NH; nh++) {
                float ev = av[nh] + ad[nh];
                ev = (ev > 0.f) ? ev : 0.2f * ev;
                float pv = __expf(ev);
                sh_p[warp][lane][nh] = pv;
                den[nh] += pv;
            }
        }
        __syncwarp();

        int j = 0;
        for (; j + 4 <= cnt; j += 4) {
            int u0 = sh_u[warp][j + 0];
            int u1 = sh_u[warp][j + 1];
            int u2 = sh_u[warp][j + 2];
            int u3 = sh_u[warp][j + 3];
            float pv0 = sh_p[warp][j + 0][hd];
            float pv1 = sh_p[warp][j + 1][hd];
            float pv2 = sh_p[warp][j + 2][hd];
            float pv3 = sh_p[warp][j + 3][hd];
            uint4 v0 = ldg_nc16(h + (size_t)u0 * HC + c0);
            uint4 v1 = ldg_nc16(h + (size_t)u1 * HC + c0);
            uint4 v2 = ldg_nc16(h + (size_t)u2 * HC + c0);
            uint4 v3 = ldg_nc16(h + (size_t)u3 * HC + c0);
            const __half2* h0 = (const __half2*)&v0;
            const __half2* h1 = (const __half2*)&v1;
            const __half2* h2 = (const __half2*)&v2;
            const __half2* h3 = (const __half2*)&v3;
#pragma unroll
            for (int q = 0; q < 4; q++) {
                float2 f0 = __half22float2(h0[q]);
                float2 f1 = __half22float2(h1[q]);
                float2 f2 = __half22float2(h2[q]);
                float2 f3 = __half22float2(h3[q]);
                acc[2 * q]     += pv0 * f0.x + pv1 * f1.x + pv2 * f2.x + pv3 * f3.x;
                acc[2 * q + 1] += pv0 * f0.y + pv1 * f1.y + pv2 * f2.y + pv3 * f3.y;
            }
        }
        for (; j < cnt; j++) {
            int u0 = sh_u[warp][j];
            float pv0 = sh_p[warp][j][hd];
            uint4 v0 = ldg_nc16(h + (size_t)u0 * HC + c0);
            const __half2* h0 = (const __half2*)&v0;
#pragma unroll
            for (int q = 0; q < 4; q++) {
                float2 f0 = __half22float2(h0[q]);
                acc[2 * q]     += pv0 * f0.x;
                acc[2 * q + 1] += pv0 * f0.y;
            }
        }
        __syncwarp();          // chunk buffer reuse
    }

#pragma unroll
    for (int nh = 0; nh < NH; nh++)
#pragma unroll
        for (int off = 16; off; off >>= 1)
            den[nh] += __shfl_xor_sync(0xffffffffu, den[nh], off);

    float invh;
    {
        float inv[NH];
#pragma unroll
        for (int nh = 0; nh < NH; nh++) inv[nh] = 1.f / (den[nh] + 1e-16f);
        if (NH == 2) invh = (hd == 0) ? inv[0] : inv[1];
        else invh = (hd < 2) ? ((hd == 0) ? inv[0] : inv[1])
                             : ((hd == 2) ? inv[2] : inv[3]);
    }

    if (DUAL) {
        float v[8];
#pragma unroll
        for (int t = 0; t < 8; t++) {
            int c = c0 + t;
            float b = (c < HC / 2) ? biasA[c] : biasB[c - HC / 2];
            v[t] = acc[t] * invh + b;
        }
        if (c0 < HC / 2) {
            float* dst = &outA[(size_t)wid * (HC / 2) + c0];
            *(float4*)dst       = make_float4(v[0], v[1], v[2], v[3]);
            *(float4*)(dst + 4) = make_float4(v[4], v[5], v[6], v[7]);
        } else {
            float* dst = &outB[(size_t)wid * (HC / 2) + (c0 - HC / 2)];
            *(float4*)dst       = make_float4(v[0], v[1], v[2], v[3]);
            *(float4*)(dst + 4) = make_float4(v[4], v[5], v[6], v[7]);
        }
    } else {
        __half hv[8];
#pragma unroll
        for (int t = 0; t < 8; t++) {
            float v = acc[t] * invh + biasA[c0 + t];
            v = (v > 0.f) ? v : expm1f(v);
            hv[t] = __float2half_rn(v);
        }
        *(uint4*)&outH[(size_t)wid * HC + c0] = *(uint4*)hv;
    }
}

// ---------------------------------------------------------------------------
// Launch — CSR + W preps on side stream; serial main chain (R13 schedule).
// ---------------------------------------------------------------------------
extern "C" void kernel_launch(void* const* d_in, const int* in_sizes, int n_in,
                              void* d_out, int out_size)
{
    const float* x         = (const float*)d_in[0];
    const unsigned int* ei = (const unsigned int*)d_in[1];
    const float* W1        = (const float*)d_in[2];
    const float* a_src1    = (const float*)d_in[3];
    const float* a_dst1    = (const float*)d_in[4];
    const float* b1        = (const float*)d_in[5];
    const float* W_mu      = (const float*)d_in[6];
    const float* a_src_mu  = (const float*)d_in[7];
    const float* a_dst_mu  = (const float*)d_in[8];
    const float* b_mu      = (const float*)d_in[9];
    const float* W_ls      = (const float*)d_in[10];
    const float* a_src_ls  = (const float*)d_in[11];
    const float* a_dst_ls  = (const float*)d_in[12];
    const float* b_ls      = (const float*)d_in[13];

    const int IN_CH = 128;
    int n  = in_sizes[0] / IN_CH;   // 50000
    int E  = in_sizes[1] / 2;       // 800000
    int EA = E + n;

    __half *hh, *x1h, *xh, *w1, *w2;
    float *as, *ad, *as2, *ad2;
    cudaGetSymbolAddress((void**)&hh,  g_hh);
    cudaGetSymbolAddress((void**)&x1h, g_x1h);
    cudaGetSymbolAddress((void**)&xh,  g_xh);
    cudaGetSymbolAddress((void**)&w1,  g_w1);
    cudaGetSymbolAddress((void**)&w2,  g_w2);
    cudaGetSymbolAddress((void**)&as,  g_as);
    cudaGetSymbolAddress((void**)&ad,  g_ad);
    cudaGetSymbolAddress((void**)&as2, g_as2);
    cudaGetSymbolAddress((void**)&ad2, g_ad2);
    int* cnt;
    cudaGetSymbolAddress((void**)&cnt, g_cnt);

    float* out_mu = (float*)d_out;
    float* out_ls = out_mu + (size_t)n * 128;

    const int TPB = 256;
    int blkEA = (EA + TPB - 1) / TPB;
    int blkN  = (n + TPB - 1) / TPB;
    int nbScan  = (n + 1023) / 1024;
    int blkWarp = (n * 32 + TPB - 1) / TPB;

    cudaFuncSetAttribute((const void*)gemm_f16<128, false, true>,
                         cudaFuncAttributeMaxDynamicSharedMemorySize, GEMMF_SMEM);
    cudaFuncSetAttribute((const void*)gemm_f16<64, true, false>,
                         cudaFuncAttributeMaxDynamicSharedMemorySize, GEMMF_SMEM);

    static cudaStream_t s1 = nullptr;
    static cudaEvent_t evFork = nullptr, evJoin = nullptr;
    if (s1 == nullptr) {
        cudaStreamCreateWithFlags(&s1, cudaStreamNonBlocking);
        cudaEventCreateWithFlags(&evFork, cudaEventDisableTiming);
        cudaEventCreateWithFlags(&evJoin, cudaEventDisableTiming);
    }

    // ---- fork: CSR build + layer-2 weight prep on side stream ----
    cudaEventRecord(evFork, 0);
    cudaStreamWaitEvent(s1, evFork, 0);
    zero_int<<<blkN, TPB, 0, s1>>>(cnt, n);
    detect64<<<1, 32, 0, s1>>>(ei);
    convert_hist<<<blkEA, TPB, 0, s1>>>(ei, E, n);
    scan_phase1<<<nbScan, 1024, 0, s1>>>(n);
    scan_phase2<<<1, 32, 0, s1>>>(nbScan);
    scan_phase3<<<nbScan, 1024, 0, s1>>>(n);
    scatter_edges<<<blkEA, TPB, 0, s1>>>(EA);
    prep_w2_f16<<<(256 * 256 + TPB - 1) / TPB, TPB, 0, s1>>>(W_mu, W_ls);
    cudaEventRecord(evJoin, s1);

    // ---- main stream: layer-1 GEMM path ----
    cast_prep1<<<(n * 128 + 256 * 128 + TPB - 1) / TPB, TPB>>>(x, W1, n * 128);
    {
        dim3 grid(2, (n + 127) / 128);
        gemm_f16<128, false, true><<<grid, 256, GEMMF_SMEM>>>(
            xh, w1, hh,
            a_src1, a_dst1, nullptr, nullptr, as, ad, n, 128, 256);
    }

    // ---- join: aggregate needs CSR + GEMM1 ----
    cudaStreamWaitEvent(0, evJoin, 0);
    aggregate<256, 128, false><<<blkWarp, TPB>>>(
        hh, as, ad, b1, nullptr, nullptr, nullptr, x1h, n);

    // ---- layer 2: fp16 GEMM (single-writer alphas) ----
    {
        dim3 grid(2, (n + 127) / 128);
        gemm_f16<64, true, false><<<grid, 256, GEMMF_SMEM>>>(
            x1h, w2, hh,
            a_src_mu, a_dst_mu, a_src_ls, a_dst_ls, as2, ad2, n, 256, 256);
    }
    aggregate<256, 64, true><<<blkWarp, TPB>>>(
        hh, as2, ad2, b_mu, b_ls, out_mu, out_ls, nullptr, n);
}

// round 17
// speedup vs baseline: 1.4616x; 1.4616x over previous
#include <cuda_runtime.h>
#include <cuda_fp16.h>
#include <math.h>
#include <cstdint>

// ---------------------------------------------------------------------------
// Problem constants
// ---------------------------------------------------------------------------
#define NMAX   50000
#define EAMAX  850000   // 800000 edges + 50000 self loops
#define NBSCAN ((NMAX + 1023) / 1024)

// ---------------------------------------------------------------------------
// Static device scratch
// ---------------------------------------------------------------------------
__device__ int   g_src[EAMAX];
__device__ int   g_dst[EAMAX];
__device__ int   g_cnt[NMAX];
__device__ int   g_rowptr[NMAX + 1];
__device__ int   g_wpos[NMAX];
__device__ int   g_srcsorted[EAMAX];
__device__ int   g_bsum[NBSCAN + 1];
__device__ int   g_is64flag;
__device__ __half g_hh [(size_t)NMAX * 256];  // GEMM output h (gather source)
__device__ __half g_x1h[(size_t)NMAX * 256];  // layer-1 output x1, fp16
__device__ __half g_xh [(size_t)NMAX * 128];  // input x, fp16
__device__ float g_as [NMAX * 2];             // layer-1 alpha_src
__device__ float g_ad [NMAX * 2];             // layer-1 alpha_dst
__device__ float g_as2[NMAX * 4];             // layer-2 alphas (mu0,mu1,ls0,ls1)
__device__ float g_ad2[NMAX * 4];
// fp16 weights (transposed [Nout][K])
__device__ __half g_w1[256 * 128];            // W1^T
__device__ __half g_w2[256 * 256];            // [W_mu|W_ls]^T

// ===========================================================================
// PTX helpers — baseline ISA only (valid at ptxas target sm_103)
// ===========================================================================
__device__ __forceinline__ uint32_t smem_to_u32(const void* p) {
    uint32_t a;
    asm("{ .reg .u64 t; cvta.to.shared.u64 t, %1; cvt.u32.u64 %0, t; }"
        : "=r"(a) : "l"(p));
    return a;
}
#define SMEM_SWIZZLE_128B(off) ((off) ^ (((off) >> 3) & 0x70))

__device__ __forceinline__ void cp_async16(uint32_t saddr, const void* gaddr) {
    asm volatile("cp.async.cg.shared.global [%0], [%1], 16;"
                 :: "r"(saddr), "l"(gaddr));
}
__device__ __forceinline__ void cp_commit() {
    asm volatile("cp.async.commit_group;");
}
__device__ __forceinline__ void cp_wait1() {
    asm volatile("cp.async.wait_group 1;");
}
__device__ __forceinline__ void cp_wait0() {
    asm volatile("cp.async.wait_group 0;");
}

__device__ __forceinline__ void ldsm4(uint32_t& r0, uint32_t& r1, uint32_t& r2,
                                      uint32_t& r3, uint32_t addr) {
    asm volatile("ldmatrix.sync.aligned.m8n8.x4.shared.b16 {%0,%1,%2,%3}, [%4];"
                 : "=r"(r0), "=r"(r1), "=r"(r2), "=r"(r3) : "r"(addr));
}

__device__ __forceinline__ void mma16816_f16(float* d, const uint32_t* a,
                                             const uint32_t* b) {
    asm volatile(
        "mma.sync.aligned.m16n8k16.row.col.f32.f16.f16.f32 "
        "{%0,%1,%2,%3}, {%4,%5,%6,%7}, {%8,%9}, {%0,%1,%2,%3};"
        : "+f"(d[0]), "+f"(d[1]), "+f"(d[2]), "+f"(d[3])
        : "r"(a[0]), "r"(a[1]), "r"(a[2]), "r"(a[3]), "r"(b[0]), "r"(b[1]));
}

// ---------------------------------------------------------------------------
// dtype probe + edge conversion + CSR build
// ---------------------------------------------------------------------------
__global__ void detect64(const unsigned int* __restrict__ raw)
{
    if (threadIdx.x == 0) {
        bool is64 = true;
#pragma unroll 1
        for (int w = 0; w < 64; w++)
            if (raw[2 * w + 1] != 0u) { is64 = false; break; }
        g_is64flag = is64 ? 1 : 0;
    }
}

__global__ void zero_int(int* __restrict__ p, int n)
{
    int i = blockIdx.x * blockDim.x + threadIdx.x;
    if (i < n) p[i] = 0;
}

__global__ void convert_hist(const unsigned int* __restrict__ raw, int E, int n)
{
    int idx = blockIdx.x * blockDim.x + threadIdx.x;
    int EA = E + n;
    if (idx >= EA) return;
    bool is64 = (g_is64flag != 0);
    int s, d;
    if (idx < E) {
        if (is64) {
            const unsigned long long* r64 = (const unsigned long long*)raw;
            s = (int)r64[idx];
            d = (int)r64[(size_t)E + idx];
        } else {
            s = (int)raw[idx];
            d = (int)raw[E + idx];
        }
    } else {
        s = idx - E;
        d = s;
    }
    g_src[idx] = s;
    g_dst[idx] = d;
    atomicAdd(&g_cnt[d], 1);
}

__global__ void scan_phase1(int n)
{
    __shared__ int sh[1024];
    int tid = threadIdx.x;
    int i = blockIdx.x * 1024 + tid;
    sh[tid] = (i < n) ? g_cnt[i] : 0;
    __syncthreads();
    for (int off = 1; off < 1024; off <<= 1) {
        int v = (tid >= off) ? sh[tid - off] : 0;
        __syncthreads();
        sh[tid] += v;
        __syncthreads();
    }
    if (i < n) g_rowptr[i + 1] = sh[tid];
    if (tid == 0) g_bsum[blockIdx.x] = sh[1023];
}

__global__ void scan_phase2(int nb)
{
    if (threadIdx.x == 0) {
        int run = 0;
        for (int b = 0; b < nb; b++) { int v = g_bsum[b]; g_bsum[b] = run; run += v; }
    }
}

__global__ void scan_phase3(int n)
{
    int tid = threadIdx.x;
    int i = blockIdx.x * 1024 + tid;
    if (i < n) {
        int v = g_rowptr[i + 1] + g_bsum[blockIdx.x];
        g_rowptr[i + 1] = v;
        if (i + 1 < n) g_wpos[i + 1] = v;     // wpos[j] = rowptr[j]
    }
    if (i == 0) { g_rowptr[0] = 0; g_wpos[0] = 0; }
}

__global__ void scatter_edges(int EA)
{
    int i = blockIdx.x * blockDim.x + threadIdx.x;
    if (i >= EA) return;
    int d = g_dst[i];
    int pos = atomicAdd(&g_wpos[d], 1);
    g_srcsorted[pos] = g_src[i];
}

// ---------------------------------------------------------------------------
// Prep: fused x->fp16 cast and W1 transpose+cast (independent index ranges)
// ---------------------------------------------------------------------------
__global__ void cast_prep1(const float* __restrict__ x,
                           const float* __restrict__ W1, int nx)
{
    int i = blockIdx.x * blockDim.x + threadIdx.x;
    if (i < nx) {
        g_xh[i] = __float2half_rn(x[i]);
    } else {
        int j = i - nx;                 // over 256*128
        if (j < 256 * 128) {
            int nout = j / 128, k = j % 128;
            g_w1[nout * 128 + k] = __float2half_rn(W1[k * 256 + nout]);
        }
    }
}

__global__ void prep_w2_f16(const float* __restrict__ Wmu, const float* __restrict__ Wls)
{
    int i = blockIdx.x * blockDim.x + threadIdx.x;   // over 256*256
    if (i >= 256 * 256) return;
    int nout = i / 256, k = i % 256;
    float v = (nout < 128) ? Wmu[k * 128 + nout] : Wls[k * 128 + (nout - 128)];
    g_w2[nout * 256 + k] = __float2half_rn(v);
}

// ---------------------------------------------------------------------------
// GEMM tiles: 128 rows x 64 fp16 = 16KB, SW128 swizzled, via cp.async.
// ---------------------------------------------------------------------------
#define GEMM_TILE   16384
#define GEMMF_BUF   (2 * GEMM_TILE)   // A, B
#define GEMMF_SMEM  (2 * GEMMF_BUF)   // 64KB, double buffered

__device__ __forceinline__ void stage_tile(uint32_t sdst, const void* gsrc,
                                           int stride, int row0, int rowmax,
                                           int k0, int tid)
{
#pragma unroll
    for (int c = tid; c < 1024; c += 256) {
        int r  = c >> 3;
        int ck = (c & 7) * 8;
        uint32_t off = (uint32_t)(r * 128 + ck * 2);
        off = SMEM_SWIZZLE_128B(off);
        int gr = row0 + r;
        if (gr > rowmax) gr = rowmax;
        cp_async16(sdst + off,
                   (const char*)gsrc + ((size_t)gr * stride + k0 + ck) * 2);
    }
}

// ---------------------------------------------------------------------------
// fp16 GEMM + fused epilogue (H fp16 + alpha dot products).
// RED=true  (C_HEAD=128): smem-reduce partials across the two warps/head.
// RED=false (C_HEAD=64) : single warp per (row, head) -> plain store.
// ---------------------------------------------------------------------------
template <int C_HEAD, bool DUAL, bool RED>
__global__ __launch_bounds__(256, 1)
void gemm_f16(const __half* __restrict__ A, const __half* __restrict__ B,
              __half* __restrict__ H,
              const float* __restrict__ avsA, const float* __restrict__ avdA,
              const float* __restrict__ avsB, const float* __restrict__ avdB,
              float* __restrict__ as_out, float* __restrict__ ad_out,
              int M, int K, int Ntot)
{
    extern __shared__ char smem[];
    uint32_t sb = smem_to_u32(smem);
    int tid  = threadIdx.x;
    int wid  = tid >> 5;
    int lane = tid & 31;

    int rowBase = blockIdx.y * 128;
    int colBase = blockIdx.x * 128;
    int warp_m  = (wid & 3) * 32;
    int warp_n  = (wid >> 2) * 64;

    int nchunks = K >> 6;

    {
        uint32_t b = sb;
        stage_tile(b + 0 * GEMM_TILE, A, K, rowBase, M - 1,    0, tid);
        stage_tile(b + 1 * GEMM_TILE, B, K, colBase, Ntot - 1, 0, tid);
        cp_commit();
    }

    float acc[2][8][4];
#pragma unroll
    for (int i = 0; i < 2; i++)
#pragma unroll
        for (int j = 0; j < 8; j++)
#pragma unroll
            for (int q = 0; q < 4; q++) acc[i][j][q] = 0.f;

    int lr = lane & 15;
    int lc = (lane & 16) >> 1;

    for (int ci = 0; ci < nchunks; ci++) {
        if (ci + 1 < nchunks) {
            uint32_t b = sb + ((ci + 1) & 1) * GEMMF_BUF;
            int k0 = (ci + 1) << 6;
            stage_tile(b + 0 * GEMM_TILE, A, K, rowBase, M - 1,    k0, tid);
            stage_tile(b + 1 * GEMM_TILE, B, K, colBase, Ntot - 1, k0, tid);
            cp_commit();
            cp_wait1();
        } else {
            cp_wait0();
        }
        __syncthreads();

        uint32_t buf = sb + (ci & 1) * GEMMF_BUF;
        uint32_t tA = buf, tB = buf + GEMM_TILE;

#pragma unroll
        for (int ks = 0; ks < 4; ks++) {
            int kb = ks * 16 + lc;

            uint32_t af[2][4];
#pragma unroll
            for (int mi = 0; mi < 2; mi++) {
                uint32_t off = (uint32_t)((warp_m + mi * 16 + lr) * 128 + kb * 2);
                off = SMEM_SWIZZLE_128B(off);
                ldsm4(af[mi][0], af[mi][1], af[mi][2], af[mi][3], tA + off);
            }
            uint32_t bf[8][2];
#pragma unroll
            for (int nb = 0; nb < 4; nb++) {
                uint32_t off = (uint32_t)((warp_n + nb * 16 + lr) * 128 + kb * 2);
                off = SMEM_SWIZZLE_128B(off);
                uint32_t q0, q1, q2, q3;
                ldsm4(q0, q1, q2, q3, tB + off);
                bf[2 * nb][0] = q0; bf[2 * nb + 1][0] = q1;
                bf[2 * nb][1] = q2; bf[2 * nb + 1][1] = q3;
            }
#pragma unroll
            for (int mi = 0; mi < 2; mi++)
#pragma unroll
                for (int nj = 0; nj < 8; nj++)
                    mma16816_f16(acc[mi][nj], af[mi], bf[nj]);
        }
        __syncthreads();
    }

    // ---- epilogue: H fp16 + alpha partials ----
    int trow = (lane >> 2);
    int tcol = (lane & 3) * 2;

    const float* avs;
    const float* avd;
    if (DUAL) {
        avs = (colBase < 128) ? avsA : avsB;
        avd = (colBase < 128) ? avdA : avdB;
    } else {
        avs = avsA;
        avd = avdA;
    }
    constexpr int NH = 256 / C_HEAD;

    __half2* H2 = (__half2*)H;
    int nh2 = Ntot >> 1;

    float ssum[2][2] = {{0.f, 0.f}, {0.f, 0.f}};
    float dsum[2][2] = {{0.f, 0.f}, {0.f, 0.f}};

#pragma unroll
    for (int mi = 0; mi < 2; mi++) {
        int gr0 = rowBase + warp_m + mi * 16 + trow;
        int gr1 = gr0 + 8;
#pragma unroll
        for (int nj = 0; nj < 8; nj++) {
            int gc = colBase + warp_n + nj * 8 + tcol;
            int ai = DUAL ? (gc - colBase) : gc;
            float w0s = avs[ai], w1s = avs[ai + 1];
            float w0d = avd[ai], w1d = avd[ai + 1];
            ssum[mi][0] += acc[mi][nj][0] * w0s + acc[mi][nj][1] * w1s;
            dsum[mi][0] += acc[mi][nj][0] * w0d + acc[mi][nj][1] * w1d;
            ssum[mi][1] += acc[mi][nj][2] * w0s + acc[mi][nj][3] * w1s;
            dsum[mi][1] += acc[mi][nj][2] * w0d + acc[mi][nj][3] * w1d;
            if (gr0 < M)
                H2[(size_t)gr0 * nh2 + (gc >> 1)] =
                    __floats2half2_rn(acc[mi][nj][0], acc[mi][nj][1]);
            if (gr1 < M)
                H2[(size_t)gr1 * nh2 + (gc >> 1)] =
                    __floats2half2_rn(acc[mi][nj][2], acc[mi][nj][3]);
        }
    }
#pragma unroll
    for (int mi = 0; mi < 2; mi++)
#pragma unroll
        for (int r = 0; r < 2; r++) {
            ssum[mi][r] += __shfl_xor_sync(0xffffffffu, ssum[mi][r], 1);
            ssum[mi][r] += __shfl_xor_sync(0xffffffffu, ssum[mi][r], 2);
            dsum[mi][r] += __shfl_xor_sync(0xffffffffu, dsum[mi][r], 1);
            dsum[mi][r] += __shfl_xor_sync(0xffffffffu, dsum[mi][r], 2);
        }

    if (RED) {
        float* sred = (float*)smem;           // tiles no longer needed
        if ((lane & 3) == 0) {
#pragma unroll
            for (int mi = 0; mi < 2; mi++)
#pragma unroll
                for (int r = 0; r < 2; r++) {
                    int lrow = mi * 16 + 8 * r + trow;   // 0..31
                    sred[wid * 32 + lrow]       = ssum[mi][r];
                    sred[256 + wid * 32 + lrow] = dsum[mi][r];
                }
        }
        __syncthreads();
        if (tid < 128) {
            int row = rowBase + tid;
            if (row < M) {
                int w0 = tid >> 5, lrow = tid & 31;
                int head = colBase >> 7;     // C_HEAD = 128
                float sv = sred[w0 * 32 + lrow] + sred[(w0 + 4) * 32 + lrow];
                float dv = sred[256 + w0 * 32 + lrow] +
                           sred[256 + (w0 + 4) * 32 + lrow];
                as_out[row * NH + head] = sv;
                ad_out[row * NH + head] = dv;
            }
        }
    } else {
        int head = (colBase + warp_n) / C_HEAD;
        if ((lane & 3) == 0) {
#pragma unroll
            for (int mi = 0; mi < 2; mi++) {
                int gr0 = rowBase + warp_m + mi * 16 + trow;
                int gr1 = gr0 + 8;
                if (gr0 < M) {
                    as_out[gr0 * NH + head] = ssum[mi][0];
                    ad_out[gr0 * NH + head] = dsum[mi][0];
                }
                if (gr1 < M) {
                    as_out[gr1 * NH + head] = ssum[mi][1];
                    ad_out[gr1 * NH + head] = dsum[mi][1];
                }
            }
        }
    }
}

// ---------------------------------------------------------------------------
// Softmax + aggregation (proven 256-thread shape, natural node order,
// plain compiler-scheduled loads — R13-exact).
// ---------------------------------------------------------------------------
template <int HC, int C, bool DUAL>
__global__ __launch_bounds__(256)
void aggregate(const __half* __restrict__ h,
               const float* __restrict__ as_in,   // [n][NH]
               const float* __restrict__ ad_in,
               const float* __restrict__ biasA,
               const float* __restrict__ biasB,
               float* __restrict__ outA,
               float* __restrict__ outB,
               __half* __restrict__ outH,
               int n)
{
    constexpr int NH = HC / C;
    __shared__ int   sh_u[8][32];
    __shared__ float sh_p[8][32][NH];

    int warp = threadIdx.x >> 5;
    int wid  = (blockIdx.x * blockDim.x + threadIdx.x) >> 5;
    int lane = threadIdx.x & 31;
    if (wid >= n) return;

    int s = g_rowptr[wid];
    int e = g_rowptr[wid + 1];

    int c0 = 8 * lane;                   // lane's first channel
    int hd = c0 / C;                     // lane's head

    float ad[NH];
    if (NH == 2) {
        float2 t = *(const float2*)&ad_in[wid * 2];
        ad[0] = t.x; ad[1] = t.y;
    } else {
        float4 t = *(const float4*)&ad_in[wid * 4];
        ad[0] = t.x; ad[1] = t.y; ad[2] = t.z; ad[3] = t.w;
    }

    float acc[8];
#pragma unroll
    for (int t = 0; t < 8; t++) acc[t] = 0.f;
    float den[NH];
#pragma unroll
    for (int nh = 0; nh < NH; nh++) den[nh] = 0.f;

    for (int base = s; base < e; base += 32) {
        int cnt = e - base; if (cnt > 32) cnt = 32;
        if (lane < cnt) {
            int u = g_srcsorted[base + lane];       // coalesced
            sh_u[warp][lane] = u;
            float av[NH];
            if (NH == 2) {
                float2 t = *(const float2*)&as_in[u * 2];
                av[0] = t.x; av[1] = t.y;
            } else {
                float4 t = *(const float4*)&as_in[u * 4];
                av[0] = t.x; av[1] = t.y; av[2] = t.z; av[3] = t.w;
            }
#pragma unroll
            for (int nh = 0; nh < NH; nh++) {
                float ev = av[nh] + ad[nh];
                ev = (ev > 0.f) ? ev : 0.2f * ev;
                float pv = __expf(ev);
                sh_p[warp][lane][nh] = pv;
                den[nh] += pv;
            }
        }
        __syncwarp();

        int j = 0;
        for (; j + 4 <= cnt; j += 4) {
            int u0 = sh_u[warp][j + 0];
            int u1 = sh_u[warp][j + 1];
            int u2 = sh_u[warp][j + 2];
            int u3 = sh_u[warp][j + 3];
            float pv0 = sh_p[warp][j + 0][hd];
            float pv1 = sh_p[warp][j + 1][hd];
            float pv2 = sh_p[warp][j + 2][hd];
            float pv3 = sh_p[warp][j + 3][hd];
            uint4 v0 = *(const uint4*)(h + (size_t)u0 * HC + c0);
            uint4 v1 = *(const uint4*)(h + (size_t)u1 * HC + c0);
            uint4 v2 = *(const uint4*)(h + (size_t)u2 * HC + c0);
            uint4 v3 = *(const uint4*)(h + (size_t)u3 * HC + c0);
            const __half2* h0 = (const __half2*)&v0;
            const __half2* h1 = (const __half2*)&v1;
            const __half2* h2 = (const __half2*)&v2;
            const __half2* h3 = (const __half2*)&v3;
#pragma unroll
            for (int q = 0; q < 4; q++) {
                float2 f0 = __half22float2(h0[q]);
                float2 f1 = __half22float2(h1[q]);
                float2 f2 = __half22float2(h2[q]);
                float2 f3 = __half22float2(h3[q]);
                acc[2 * q]     += pv0 * f0.x + pv1 * f1.x + pv2 * f2.x + pv3 * f3.x;
                acc[2 * q + 1] += pv0 * f0.y + pv1 * f1.y + pv2 * f2.y + pv3 * f3.y;
            }
        }
        for (; j < cnt; j++) {
            int u0 = sh_u[warp][j];
            float pv0 = sh_p[warp][j][hd];
            uint4 v0 = *(const uint4*)(h + (size_t)u0 * HC + c0);
            const __half2* h0 = (const __half2*)&v0;
#pragma unroll
            for (int q = 0; q < 4; q++) {
                float2 f0 = __half22float2(h0[q]);
                acc[2 * q]     += pv0 * f0.x;
                acc[2 * q + 1] += pv0 * f0.y;
            }
        }
        __syncwarp();          // chunk buffer reuse
    }

#pragma unroll
    for (int nh = 0; nh < NH; nh++)
#pragma unroll
        for (int off = 16; off; off >>= 1)
            den[nh] += __shfl_xor_sync(0xffffffffu, den[nh], off);

    float invh;
    {
        float inv[NH];
#pragma unroll
        for (int nh = 0; nh < NH; nh++) inv[nh] = 1.f / (den[nh] + 1e-16f);
        if (NH == 2) invh = (hd == 0) ? inv[0] : inv[1];
        else invh = (hd < 2) ? ((hd == 0) ? inv[0] : inv[1])
                             : ((hd == 2) ? inv[2] : inv[3]);
    }

    if (DUAL) {
        float v[8];
#pragma unroll
        for (int t = 0; t < 8; t++) {
            int c = c0 + t;
            float b = (c < HC / 2) ? biasA[c] : biasB[c - HC / 2];
            v[t] = acc[t] * invh + b;
        }
        if (c0 < HC / 2) {
            float* dst = &outA[(size_t)wid * (HC / 2) + c0];
            *(float4*)dst       = make_float4(v[0], v[1], v[2], v[3]);
            *(float4*)(dst + 4) = make_float4(v[4], v[5], v[6], v[7]);
        } else {
            float* dst = &outB[(size_t)wid * (HC / 2) + (c0 - HC / 2)];
            *(float4*)dst       = make_float4(v[0], v[1], v[2], v[3]);
            *(float4*)(dst + 4) = make_float4(v[4], v[5], v[6], v[7]);
        }
    } else {
        __half hv[8];
#pragma unroll
        for (int t = 0; t < 8; t++) {
            float v = acc[t] * invh + biasA[c0 + t];
            v = (v > 0.f) ? v : expm1f(v);
            hv[t] = __float2half_rn(v);
        }
        *(uint4*)&outH[(size_t)wid * HC + c0] = *(uint4*)hv;
    }
}

// ---------------------------------------------------------------------------
// Launch — CSR + W preps on side stream; serial main chain (R13 schedule).
// ---------------------------------------------------------------------------
extern "C" void kernel_launch(void* const* d_in, const int* in_sizes, int n_in,
                              void* d_out, int out_size)
{
    const float* x         = (const float*)d_in[0];
    const unsigned int* ei = (const unsigned int*)d_in[1];
    const float* W1        = (const float*)d_in[2];
    const float* a_src1    = (const float*)d_in[3];
    const float* a_dst1    = (const float*)d_in[4];
    const float* b1        = (const float*)d_in[5];
    const float* W_mu      = (const float*)d_in[6];
    const float* a_src_mu  = (const float*)d_in[7];
    const float* a_dst_mu  = (const float*)d_in[8];
    const float* b_mu      = (const float*)d_in[9];
    const float* W_ls      = (const float*)d_in[10];
    const float* a_src_ls  = (const float*)d_in[11];
    const float* a_dst_ls  = (const float*)d_in[12];
    const float* b_ls      = (const float*)d_in[13];

    const int IN_CH = 128;
    int n  = in_sizes[0] / IN_CH;   // 50000
    int E  = in_sizes[1] / 2;       // 800000
    int EA = E + n;

    __half *hh, *x1h, *xh, *w1, *w2;
    float *as, *ad, *as2, *ad2;
    cudaGetSymbolAddress((void**)&hh,  g_hh);
    cudaGetSymbolAddress((void**)&x1h, g_x1h);
    cudaGetSymbolAddress((void**)&xh,  g_xh);
    cudaGetSymbolAddress((void**)&w1,  g_w1);
    cudaGetSymbolAddress((void**)&w2,  g_w2);
    cudaGetSymbolAddress((void**)&as,  g_as);
    cudaGetSymbolAddress((void**)&ad,  g_ad);
    cudaGetSymbolAddress((void**)&as2, g_as2);
    cudaGetSymbolAddress((void**)&ad2, g_ad2);
    int* cnt;
    cudaGetSymbolAddress((void**)&cnt, g_cnt);

    float* out_mu = (float*)d_out;
    float* out_ls = out_mu + (size_t)n * 128;

    const int TPB = 256;
    int blkEA = (EA + TPB - 1) / TPB;
    int blkN  = (n + TPB - 1) / TPB;
    int nbScan  = (n + 1023) / 1024;
    int blkWarp = (n * 32 + TPB - 1) / TPB;

    cudaFuncSetAttribute((const void*)gemm_f16<128, false, true>,
                         cudaFuncAttributeMaxDynamicSharedMemorySize, GEMMF_SMEM);
    cudaFuncSetAttribute((const void*)gemm_f16<64, true, false>,
                         cudaFuncAttributeMaxDynamicSharedMemorySize, GEMMF_SMEM);

    static cudaStream_t s1 = nullptr;
    static cudaEvent_t evFork = nullptr, evJoin = nullptr;
    if (s1 == nullptr) {
        cudaStreamCreateWithFlags(&s1, cudaStreamNonBlocking);
        cudaEventCreateWithFlags(&evFork, cudaEventDisableTiming);
        cudaEventCreateWithFlags(&evJoin, cudaEventDisableTiming);
    }

    // ---- fork: CSR build + layer-2 weight prep on side stream ----
    cudaEventRecord(evFork, 0);
    cudaStreamWaitEvent(s1, evFork, 0);
    zero_int<<<blkN, TPB, 0, s1>>>(cnt, n);
    detect64<<<1, 32, 0, s1>>>(ei);
    convert_hist<<<blkEA, TPB, 0, s1>>>(ei, E, n);
    scan_phase1<<<nbScan, 1024, 0, s1>>>(n);
    scan_phase2<<<1, 32, 0, s1>>>(nbScan);
    scan_phase3<<<nbScan, 1024, 0, s1>>>(n);
    scatter_edges<<<blkEA, TPB, 0, s1>>>(EA);
    prep_w2_f16<<<(256 * 256 + TPB - 1) / TPB, TPB, 0, s1>>>(W_mu, W_ls);
    cudaEventRecord(evJoin, s1);

    // ---- main stream: layer-1 GEMM path ----
    cast_prep1<<<(n * 128 + 256 * 128 + TPB - 1) / TPB, TPB>>>(x, W1, n * 128);
    {
        dim3 grid(2, (n + 127) / 128);
        gemm_f16<128, false, true><<<grid, 256, GEMMF_SMEM>>>(
            xh, w1, hh,
            a_src1, a_dst1, nullptr, nullptr, as, ad, n, 128, 256);
    }

    // ---- join: aggregate needs CSR + GEMM1 ----
    cudaStreamWaitEvent(0, evJoin, 0);
    aggregate<256, 128, false><<<blkWarp, TPB>>>(
        hh, as, ad, b1, nullptr, nullptr, nullptr, x1h, n);

    // ---- layer 2: fp16 GEMM (single-writer alphas) ----
    {
        dim3 grid(2, (n + 127) / 128);
        gemm_f16<64, true, false><<<grid, 256, GEMMF_SMEM>>>(
            x1h, w2, hh,
            a_src_mu, a_dst_mu, a_src_ls, a_dst_ls, as2, ad2, n, 256, 256);
    }
    aggregate<256, 64, true><<<blkWarp, TPB>>>(
        hh, as2, ad2, b_mu, b_ls, out_mu, out_ls, nullptr, n);
}